// round 6
// baseline (speedup 1.0000x reference)
#include <cuda_runtime.h>
#include <cuda_fp16.h>
#include <cstdint>

// LorentzConv1d via single-pass fp16 mma.sync m16n8k16 (fp32 accum).
// 1024-thread CTA, 32 warps, warp tile 16 rows x 32 cols (occupancy-optimized).
// K permuted into 160 pairs so every mma k-pair is one aligned LDS.32 (see r5).
// B staged as nb-paired uint4 units -> 2 conflict-free LDS.128 per warp-kb.
// t_resc is an fp32 rank-1 epilogue term; Lorentz norm via cross-warp smem partials.

#define LLEN 8192
#define CIN  64
#define MT   256
#define XPS  68
#define XRS  34
#define NR   260
#define XP_OFF  0
#define XR_OFF  (NR * XPS)            // 17680
#define TR_OFF  (XR_OFF + NR * XRS)   // 26520
#define WB4_OFF (TR_OFF + 256)        // 26776 (16B aligned)
#define PS_OFF  (WB4_OFF + 128)       // 26904 (512 floats)
#define ZW_OFF  (PS_OFF + 512)        // 27416
#define B_OFF   (ZW_OFF + 8)          // 27424 (16B aligned)
#define LGSTR   41                    // uint4 units per lane slot (odd -> conflict-free)
#define NGSTR   (32 * LGSTR)          // 1312
#define B_U4    (2 * NGSTR)           // 2624
#define SMEM_WORDS (B_OFF + B_U4 * 4) // 37920
#define SMEM_BYTES (SMEM_WORDS * 4)   // 151680

__device__ __forceinline__ uint32_t h2pack(float a, float b) {
    __half2 h = __floats2half2_rn(a, b);
    return *(uint32_t*)&h;
}
__device__ __forceinline__ void mma_f16(float* d, const uint32_t* a, uint32_t b0, uint32_t b1) {
    asm volatile(
        "mma.sync.aligned.m16n8k16.row.col.f32.f16.f16.f32 "
        "{%0,%1,%2,%3}, {%4,%5,%6,%7}, {%8,%9}, {%0,%1,%2,%3};"
        : "+f"(d[0]), "+f"(d[1]), "+f"(d[2]), "+f"(d[3])
        : "r"(a[0]), "r"(a[1]), "r"(a[2]), "r"(a[3]), "r"(b0), "r"(b1));
}
// W value for permuted slot s = 2p + t:
//   p 0..125  : channel c=(p>>1)+1, tap (p&1)*2+t
//   p 126..157: tap 4, channel 2*(p-126)+t
//   p 158..159: zero
__device__ __forceinline__ float slotW(const float* __restrict__ Wr, int p, int t) {
    if (p >= 158) return 0.f;
    if (p >= 126) {
        int ch = 2 * (p - 126) + t;
        return (ch == 0) ? 0.f : Wr[(ch - 1) * 5 + 5];
    }
    int c = (p >> 1) + 1;
    int kk = (p & 1) * 2 + t;
    return Wr[(c - 1) * 5 + kk + 1];
}

__global__ __launch_bounds__(1024, 1)
void lorentz_f16_kernel(const float* __restrict__ x,
                        const float* __restrict__ W,
                        const float* __restrict__ bvec,
                        float* __restrict__ out)
{
    extern __shared__ uint32_t sm[];
    float*  tr  = (float*)(sm + TR_OFF);
    float4* wb4 = (float4*)(sm + WB4_OFF);
    float*  ps  = (float*)(sm + PS_OFF);
    uint4*  BQ4 = (uint4*)(sm + B_OFF);

    const int tid  = threadIdx.x;
    const int wid  = tid >> 5;
    const int lane = tid & 31;
    const int bidx = blockIdx.x >> 5;          // 32 tiles per batch
    const int l0   = (blockIdx.x & 31) << 8;   // 256 rows per tile

    if (tid < 8) sm[ZW_OFF + tid] = 0;

    // ---- stage xp (row-pair packed fp16) and xr (row-major fp16) ----
    const float* xb = x + (size_t)bidx * (LLEN * CIN);
    for (int idx = tid; idx < NR * 16; idx += 1024) {
        int r = idx >> 4, c4 = idx & 15;
        int g = l0 - 2 + r;
        float4 v0, v1;
        if ((unsigned)g < (unsigned)LLEN) v0 = *(const float4*)(xb + (size_t)g * CIN + c4 * 4);
        else { v0 = make_float4(0.f, 0.f, 0.f, 0.f); if (c4 == 0) v0.x = 1.0f; }
        if ((unsigned)(g + 1) < (unsigned)LLEN) v1 = *(const float4*)(xb + (size_t)(g + 1) * CIN + c4 * 4);
        else { v1 = make_float4(0.f, 0.f, 0.f, 0.f); if (c4 == 0) v1.x = 1.0f; }
        uint4 pw;
        pw.x = h2pack(v0.x, v1.x); pw.y = h2pack(v0.y, v1.y);
        pw.z = h2pack(v0.z, v1.z); pw.w = h2pack(v0.w, v1.w);
        *(uint4*)(sm + XP_OFF + r * XPS + c4 * 4) = pw;
        uint2 rw;
        rw.x = h2pack(v0.x, v0.y); rw.y = h2pack(v0.z, v0.w);
        *(uint2*)(sm + XR_OFF + r * XRS + c4 * 2) = rw;
    }

    // ---- t_resc per output row, exact fp32 from global ----
    if (tid < MT) {
        int g0 = l0 + tid - 2;
        float s = -4.0f;
#pragma unroll
        for (int k = 0; k < 5; k++) {
            int g = g0 + k;
            float t = ((unsigned)g < (unsigned)LLEN) ? xb[(size_t)g * CIN] : 1.0f;
            s = fmaf(t, t, s);
        }
        tr[tid] = sqrtf(s);
    }

    // ---- stage B: uint4 = (bx, by of nb=2nbp | bx, by of nb=2nbp+1) per (ngrp, lg, kb) ----
    for (int u = tid; u < B_U4; u += 1024) {
        int ngrp = u / NGSTR;
        int rem  = u - ngrp * NGSTR;
        int lg   = rem / (LGSTR);              // 0..31, but only 0..40 cols used per lg
        int t2   = rem - lg * LGSTR;           // 0..40 (last unit is pad)
        if (t2 >= 40) continue;
        int kb  = t2 >> 1;
        int nbp = t2 & 1;
        int q4g = lg >> 2, s4g = lg & 3;
        int n0  = (ngrp * 4 + 2 * nbp) * 8 + q4g;
        int n1  = n0 + 8;
        int p0  = 8 * kb + s4g, p2 = p0 + 4;
        const float* W0 = W + (size_t)n0 * 316;
        const float* W1 = W + (size_t)n1 * 316;
        uint4 w;
        w.x = h2pack(slotW(W0, p0, 0), slotW(W0, p0, 1));
        w.y = h2pack(slotW(W0, p2, 0), slotW(W0, p2, 1));
        w.z = h2pack(slotW(W1, p0, 0), slotW(W1, p0, 1));
        w.w = h2pack(slotW(W1, p2, 0), slotW(W1, p2, 1));
        BQ4[u] = w;
    }

    // ---- fp32 time-weight + bias pairs: wb4[i] for col pair (2i, 2i+1) ----
    if (tid < 32) {
        wb4[tid] = make_float4(W[(size_t)(2 * tid) * 316], bvec[2 * tid],
                               W[(size_t)(2 * tid + 1) * 316], bvec[2 * tid + 1]);
    }
    __syncthreads();

    // ---- mainloop: warp tile 16 rows x 32 cols ----
    const int q4   = lane >> 2;
    const int s4   = lane & 3;
    const int ngrp = wid & 1;
    const int rowa = (wid >> 1) * 16 + q4;     // 0..247

    const int bxp0 = XP_OFF + (rowa + 2 * (s4 & 1)) * XPS + (s4 >> 1) + 1;
    const int bxp1 = bxp0 + 8 * XPS;
    const int bxr0 = XR_OFF + (rowa + 4) * XRS + s4 - 126;
    const int bxr1 = bxr0 + 8 * XRS;
    const int ub   = ngrp * NGSTR + lane * LGSTR;

    float d[4][4];
#pragma unroll
    for (int nb = 0; nb < 4; nb++) { d[nb][0] = d[nb][1] = d[nb][2] = d[nb][3] = 0.f; }

#pragma unroll
    for (int kb = 0; kb < 20; kb++) {
        int A0, A1, A2, A3;
        if (kb <= 14) {
            A0 = bxp0 + 4 * kb; A1 = bxp1 + 4 * kb; A2 = A0 + 2; A3 = A1 + 2;
        } else if (kb == 15) {
            A0 = bxp0 + 60; A1 = bxp1 + 60;
            A2 = (s4 < 2) ? (bxp0 + 62) : (bxr0 + 124);
            A3 = (s4 < 2) ? (bxp1 + 62) : (bxr1 + 124);
        } else if (kb <= 18) {
            A0 = bxr0 + 8 * kb; A1 = bxr1 + 8 * kb; A2 = A0 + 4; A3 = A1 + 4;
        } else {
            A0 = bxr0 + 152; A1 = bxr1 + 152;
            A2 = (s4 < 2) ? (bxr0 + 156) : ZW_OFF;
            A3 = (s4 < 2) ? (bxr1 + 156) : ZW_OFF;
        }
        uint32_t a[4];
        a[0] = sm[A0]; a[1] = sm[A1]; a[2] = sm[A2]; a[3] = sm[A3];
        uint4 b0 = BQ4[ub + kb * 2 + 0];
        uint4 b1 = BQ4[ub + kb * 2 + 1];
        mma_f16(d[0], a, b0.x, b0.y);
        mma_f16(d[1], a, b0.z, b0.w);
        mma_f16(d[2], a, b1.x, b1.y);
        mma_f16(d[3], a, b1.z, b1.w);
    }

    // ---- epilogue: + W[:,0]*t_resc + b, cross-warp Lorentz norm, store ----
    const float tra = tr[rowa];
    const float trb = tr[rowa + 8];
    float ssa = 0.f, ssb = 0.f;
#pragma unroll
    for (int nb = 0; nb < 4; nb++) {
        float4 f4 = wb4[(ngrp * 4 + nb) * 4 + s4];
        float y0 = fmaf(f4.x, tra, d[nb][0]) + f4.y;
        float y1 = fmaf(f4.z, tra, d[nb][1]) + f4.w;
        float y2 = fmaf(f4.x, trb, d[nb][2]) + f4.y;
        float y3 = fmaf(f4.z, trb, d[nb][3]) + f4.w;
        if (!(ngrp == 0 && nb == 0 && s4 == 0)) {   // global col 0 excluded from the norm
            ssa = fmaf(y0, y0, ssa);
            ssb = fmaf(y2, y2, ssb);
        }
        ssa = fmaf(y1, y1, ssa);
        ssb = fmaf(y3, y3, ssb);
        d[nb][0] = y0; d[nb][1] = y1; d[nb][2] = y2; d[nb][3] = y3;
    }
    ssa += __shfl_xor_sync(0xffffffffu, ssa, 1);
    ssa += __shfl_xor_sync(0xffffffffu, ssa, 2);
    ssb += __shfl_xor_sync(0xffffffffu, ssb, 1);
    ssb += __shfl_xor_sync(0xffffffffu, ssb, 2);
    if (s4 == 0) {
        ps[rowa * 2 + ngrp]       = ssa;
        ps[(rowa + 8) * 2 + ngrp] = ssb;
    }
    __syncthreads();
    if (ngrp == 0 && s4 == 0) {
        d[0][0] = sqrtf(ps[rowa * 2] + ps[rowa * 2 + 1] + 1.0f);
        d[0][2] = sqrtf(ps[(rowa + 8) * 2] + ps[(rowa + 8) * 2 + 1] + 1.0f);
    }

    const size_t oa = ((size_t)bidx * LLEN + (size_t)(l0 + rowa)) * 64 + ngrp * 32 + 2 * s4;
    const size_t ob = oa + 8 * 64;
#pragma unroll
    for (int nb = 0; nb < 4; nb++) {
        *(float2*)(out + oa + nb * 8) = make_float2(d[nb][0], d[nb][1]);
        *(float2*)(out + ob + nb * 8) = make_float2(d[nb][2], d[nb][3]);
    }
}

extern "C" void kernel_launch(void* const* d_in, const int* in_sizes, int n_in,
                              void* d_out, int out_size)
{
    const float* x = (const float*)d_in[0];
    const float* W = (const float*)d_in[1];
    const float* b = (const float*)d_in[2];
    float* out = (float*)d_out;

    cudaFuncSetAttribute(lorentz_f16_kernel,
                         cudaFuncAttributeMaxDynamicSharedMemorySize, SMEM_BYTES);
    lorentz_f16_kernel<<<512, 1024, SMEM_BYTES>>>(x, W, b, out);
}

// round 7
// speedup vs baseline: 1.4261x; 1.4261x over previous
#include <cuda_runtime.h>
#include <cuda_fp16.h>
#include <cstdint>

// LorentzConv1d via single-pass fp16 mma.sync m16n8k16 (fp32 accum).
// Warp tile 32x64 (2 M-blocks x 8 N-blocks), 16 warps, MT=512 rows/CTA, grid=256.
//
// K permutation: 192 pairs (K=384). Pair table (p = kb*8 + slot):
//   chg = p/12, within = p%12, kk = 2*(within/4), c = 4*chg + 1 + (within%4)
//   pair = taps (kk, kk+1) of channel c; tap 5 and c=64 are zero B slots
//   (A word for (4,notdef) = {x[r+4,c], x[r+5,c]}; second elem multiplies B=0).
// A word = xp[(lrow+kk)*XPS + c], xp[r][c] = {h(x[r,c]), h(x[r+1,c])}.
// Bank index = 4*q4 + s4 + const -> conflict-free A loads (XPS=68 = 4 mod 32).
// t_resc is an fp32 rank-1 epilogue term; Lorentz norm in-warp over s4.

#define LLEN 8192
#define CIN  64
#define MT   512
#define XPS  68
#define NR   516
#define TR_OFF  (NR * XPS)            // 35088
#define WB4_OFF (TR_OFF + 512)        // 35600 (16B aligned)
#define B_OFF   (WB4_OFF + 128)       // 35728 (16B aligned)
#define LGSTR   97                    // uint4 units per lane slot (24*4 + 1, odd)
#define B_UNITS (32 * LGSTR)          // 3104
#define SMEM_WORDS (B_OFF + B_UNITS * 4)  // 48144
#define SMEM_BYTES (SMEM_WORDS * 4)       // 192576

__device__ __forceinline__ uint32_t h2pack(float a, float b) {
    __half2 h = __floats2half2_rn(a, b);
    return *(uint32_t*)&h;
}
__device__ __forceinline__ void mma_f16(float* d, const uint32_t* a, uint32_t b0, uint32_t b1) {
    asm volatile(
        "mma.sync.aligned.m16n8k16.row.col.f32.f16.f16.f32 "
        "{%0,%1,%2,%3}, {%4,%5,%6,%7}, {%8,%9}, {%0,%1,%2,%3};"
        : "+f"(d[0]), "+f"(d[1]), "+f"(d[2]), "+f"(d[3])
        : "r"(a[0]), "r"(a[1]), "r"(a[2]), "r"(a[3]), "r"(b0), "r"(b1));
}
// W value for pair slot p, element t (0/1)
__device__ __forceinline__ float slotW(const float* __restrict__ W, int n, int p, int t) {
    int chg = (p * 683) >> 13;          // p/12 for p < 192
    int within = p - 12 * chg;
    int kk = 2 * (within >> 2);
    int cc = 4 * chg + 1 + (within & 3);
    int tap = kk + t;
    if (cc > 63 || tap > 4) return 0.f;
    return W[(size_t)n * 316 + (cc - 1) * 5 + tap + 1];
}

__global__ __launch_bounds__(512, 1)
void lorentz_f16_kernel(const float* __restrict__ x,
                        const float* __restrict__ W,
                        const float* __restrict__ bvec,
                        float* __restrict__ out)
{
    extern __shared__ uint32_t sm[];
    float*  tr  = (float*)(sm + TR_OFF);
    float4* wb4 = (float4*)(sm + WB4_OFF);
    uint4*  BQ4 = (uint4*)(sm + B_OFF);

    const int tid  = threadIdx.x;
    const int wid  = tid >> 5;
    const int lane = tid & 31;
    const int bidx = blockIdx.x >> 4;          // 16 tiles per batch
    const int l0   = (blockIdx.x & 15) << 9;   // 512 rows per tile

    // ---- stage xp (row-pair packed fp16), zero the pad columns 64..67 ----
    const float* xb = x + (size_t)bidx * (LLEN * CIN);
    for (int idx = tid; idx < NR * 16; idx += 512) {
        int r = idx >> 4, c4 = idx & 15;
        int g = l0 - 2 + r;
        float4 v0, v1;
        if ((unsigned)g < (unsigned)LLEN) v0 = *(const float4*)(xb + (size_t)g * CIN + c4 * 4);
        else { v0 = make_float4(0.f, 0.f, 0.f, 0.f); if (c4 == 0) v0.x = 1.0f; }
        if ((unsigned)(g + 1) < (unsigned)LLEN) v1 = *(const float4*)(xb + (size_t)(g + 1) * CIN + c4 * 4);
        else { v1 = make_float4(0.f, 0.f, 0.f, 0.f); if (c4 == 0) v1.x = 1.0f; }
        uint4 pw;
        pw.x = h2pack(v0.x, v1.x); pw.y = h2pack(v0.y, v1.y);
        pw.z = h2pack(v0.z, v1.z); pw.w = h2pack(v0.w, v1.w);
        *(uint4*)(sm + r * XPS + c4 * 4) = pw;
    }
    for (int r = tid; r < NR; r += 512)
        *(uint4*)(sm + r * XPS + 64) = make_uint4(0, 0, 0, 0);

    // ---- t_resc per output row, exact fp32 from global ----
    {
        int g0 = l0 + tid - 2;
        float s = -4.0f;
#pragma unroll
        for (int k = 0; k < 5; k++) {
            int g = g0 + k;
            float t = ((unsigned)g < (unsigned)LLEN) ? xb[(size_t)g * CIN] : 1.0f;
            s = fmaf(t, t, s);
        }
        tr[tid] = sqrtf(s);
    }

    // ---- stage B: unit (lg, kb, i) = (b0,b1 of n=16i+q4g | b0,b1 of n=16i+8+q4g) ----
    for (int u = tid; u < 32 * 24 * 4; u += 512) {
        int i  = u & 3;
        int t2 = u >> 2;
        int kb = t2 % 24;
        int lg = t2 / 24;                      // 0..31
        int q4g = lg >> 2, s4g = lg & 3;
        int n0 = 16 * i + q4g;
        int n1 = n0 + 8;
        int p0 = kb * 8 + s4g, p2 = p0 + 4;
        uint4 w;
        w.x = h2pack(slotW(W, n0, p0, 0), slotW(W, n0, p0, 1));
        w.y = h2pack(slotW(W, n0, p2, 0), slotW(W, n0, p2, 1));
        w.z = h2pack(slotW(W, n1, p0, 0), slotW(W, n1, p0, 1));
        w.w = h2pack(slotW(W, n1, p2, 0), slotW(W, n1, p2, 1));
        BQ4[lg * LGSTR + kb * 4 + i] = w;
    }

    // ---- fp32 time-weight + bias pairs ----
    if (tid < 32) {
        wb4[tid] = make_float4(W[(size_t)(2 * tid) * 316], bvec[2 * tid],
                               W[(size_t)(2 * tid + 1) * 316], bvec[2 * tid + 1]);
    }
    __syncthreads();

    // ---- mainloop: warp tile 32 rows x 64 cols, 24 k-blocks ----
    const int q4   = lane >> 2;
    const int s4   = lane & 3;
    const int wrow = wid * 32;
    const int bx   = (wrow + q4) * XPS + s4;   // A base (word index)
    const int ub   = (q4 * 4 + s4) * LGSTR;    // B base (uint4 index)

    float d[2][8][4];
#pragma unroll
    for (int m = 0; m < 2; m++)
#pragma unroll
        for (int nb = 0; nb < 8; nb++)
            d[m][nb][0] = d[m][nb][1] = d[m][nb][2] = d[m][nb][3] = 0.f;

#pragma unroll
    for (int kb = 0; kb < 24; kb++) {
        const int sub0 = 2 * kb, sub1 = 2 * kb + 1;
        const int kk0 = 2 * (sub0 % 3), cb0 = 4 * (sub0 / 3) + 1;
        const int kk1 = 2 * (sub1 % 3), cb1 = 4 * (sub1 / 3) + 1;

        uint4 b0 = BQ4[ub + kb * 4 + 0];
        uint4 b1 = BQ4[ub + kb * 4 + 1];
        uint4 b2 = BQ4[ub + kb * 4 + 2];
        uint4 b3 = BQ4[ub + kb * 4 + 3];

#pragma unroll
        for (int m = 0; m < 2; m++) {
            uint32_t a[4];
            a[0] = sm[bx + (kk0 + 16 * m) * XPS + cb0];
            a[1] = sm[bx + (kk0 + 16 * m + 8) * XPS + cb0];
            a[2] = sm[bx + (kk1 + 16 * m) * XPS + cb1];
            a[3] = sm[bx + (kk1 + 16 * m + 8) * XPS + cb1];
            mma_f16(d[m][0], a, b0.x, b0.y);
            mma_f16(d[m][1], a, b0.z, b0.w);
            mma_f16(d[m][2], a, b1.x, b1.y);
            mma_f16(d[m][3], a, b1.z, b1.w);
            mma_f16(d[m][4], a, b2.x, b2.y);
            mma_f16(d[m][5], a, b2.z, b2.w);
            mma_f16(d[m][6], a, b3.x, b3.y);
            mma_f16(d[m][7], a, b3.z, b3.w);
        }
    }

    // ---- epilogue: + W[:,0]*t_resc + b, Lorentz norm (in-warp over s4), store ----
#pragma unroll
    for (int m = 0; m < 2; m++) {
        const int ra = wrow + 16 * m + q4;
        const float tra = tr[ra];
        const float trb = tr[ra + 8];
        float ssa = 0.f, ssb = 0.f;
#pragma unroll
        for (int nb = 0; nb < 8; nb++) {
            float4 f4 = wb4[nb * 4 + s4];
            float y0 = fmaf(f4.x, tra, d[m][nb][0]) + f4.y;
            float y1 = fmaf(f4.z, tra, d[m][nb][1]) + f4.w;
            float y2 = fmaf(f4.x, trb, d[m][nb][2]) + f4.y;
            float y3 = fmaf(f4.z, trb, d[m][nb][3]) + f4.w;
            if (!(nb == 0 && s4 == 0)) {       // global col 0 excluded from the norm
                ssa = fmaf(y0, y0, ssa);
                ssb = fmaf(y2, y2, ssb);
            }
            ssa = fmaf(y1, y1, ssa);
            ssb = fmaf(y3, y3, ssb);
            d[m][nb][0] = y0; d[m][nb][1] = y1;
            d[m][nb][2] = y2; d[m][nb][3] = y3;
        }
        ssa += __shfl_xor_sync(0xffffffffu, ssa, 1);
        ssa += __shfl_xor_sync(0xffffffffu, ssa, 2);
        ssb += __shfl_xor_sync(0xffffffffu, ssb, 1);
        ssb += __shfl_xor_sync(0xffffffffu, ssb, 2);
        if (s4 == 0) {
            d[m][0][0] = sqrtf(ssa + 1.0f);
            d[m][0][2] = sqrtf(ssb + 1.0f);
        }

        const size_t oa = ((size_t)bidx * LLEN + (size_t)(l0 + ra)) * 64 + 2 * s4;
        const size_t ob = oa + 8 * 64;
#pragma unroll
        for (int nb = 0; nb < 8; nb++) {
            *(float2*)(out + oa + nb * 8) = make_float2(d[m][nb][0], d[m][nb][1]);
            *(float2*)(out + ob + nb * 8) = make_float2(d[m][nb][2], d[m][nb][3]);
        }
    }
}

extern "C" void kernel_launch(void* const* d_in, const int* in_sizes, int n_in,
                              void* d_out, int out_size)
{
    const float* x = (const float*)d_in[0];
    const float* W = (const float*)d_in[1];
    const float* b = (const float*)d_in[2];
    float* out = (float*)d_out;

    cudaFuncSetAttribute(lorentz_f16_kernel,
                         cudaFuncAttributeMaxDynamicSharedMemorySize, SMEM_BYTES);
    lorentz_f16_kernel<<<256, 512, SMEM_BYTES>>>(x, W, b, out);
}

// round 8
// speedup vs baseline: 1.4591x; 1.0231x over previous
#include <cuda_runtime.h>
#include <cuda_fp16.h>
#include <cstdint>

// LorentzConv1d via single-pass fp16 mma.sync m16n8k16 (fp32 accum).
// Warp tile 32x64, 16 warps, MT=512 rows/CTA, grid=256.
// Round 8: warp-private A staging (no CTA barrier between stage and compute);
// only B/wb4 keep one early __syncthreads. t_resc recomputed in epilogue.
//
// K permutation (K=384, 192 pairs), p = kb*8 + slot:
//   chg = p/12, within = p%12, kk = 2*(within/4), c = 4*chg + 1 + (within%4)
//   pair = taps (kk, kk+1) of channel c; tap 5 and c=64 are zero B slots.
// A word = xp_w[(i+kk)*XPS + c] where xp_w[r][c] = {h(x[g+r,c]), h(x[g+r+1,c])},
// g = l0 + wid*32 - 2. Bank = 4*q4 + s4 + const -> conflict-free.

#define LLEN 8192
#define CIN  64
#define MT   512
#define XPS  68
#define WPRIV (36 * XPS)              // 2448 words per warp
#define WB4_OFF (16 * WPRIV)          // 39168 (16B aligned)
#define B_OFF   (WB4_OFF + 128)       // 39296 (16B aligned)
#define LGSTR   97                    // uint4 units per lane slot (24*4 + 1, odd)
#define B_UNITS (32 * LGSTR)          // 3104
#define SMEM_WORDS (B_OFF + B_UNITS * 4)  // 51712
#define SMEM_BYTES (SMEM_WORDS * 4)       // 206848

__device__ __forceinline__ uint32_t h2pack(float a, float b) {
    __half2 h = __floats2half2_rn(a, b);
    return *(uint32_t*)&h;
}
__device__ __forceinline__ void mma_f16(float* d, const uint32_t* a, uint32_t b0, uint32_t b1) {
    asm volatile(
        "mma.sync.aligned.m16n8k16.row.col.f32.f16.f16.f32 "
        "{%0,%1,%2,%3}, {%4,%5,%6,%7}, {%8,%9}, {%0,%1,%2,%3};"
        : "+f"(d[0]), "+f"(d[1]), "+f"(d[2]), "+f"(d[3])
        : "r"(a[0]), "r"(a[1]), "r"(a[2]), "r"(a[3]), "r"(b0), "r"(b1));
}
// W value for pair slot p, element t (0/1)
__device__ __forceinline__ float slotW(const float* __restrict__ W, int n, int p, int t) {
    int chg = (p * 683) >> 13;          // p/12 for p < 192
    int within = p - 12 * chg;
    int kk = 2 * (within >> 2);
    int cc = 4 * chg + 1 + (within & 3);
    int tap = kk + t;
    if (cc > 63 || tap > 4) return 0.f;
    return W[(size_t)n * 316 + (cc - 1) * 5 + tap + 1];
}
__device__ __forceinline__ float tresc(const float* __restrict__ xb, int l) {
    float s = -4.0f;
#pragma unroll
    for (int k = 0; k < 5; k++) {
        int g = l - 2 + k;
        float t = ((unsigned)g < (unsigned)LLEN) ? xb[(size_t)g * CIN] : 1.0f;
        s = fmaf(t, t, s);
    }
    return sqrtf(s);
}

__global__ __launch_bounds__(512, 1)
void lorentz_f16_kernel(const float* __restrict__ x,
                        const float* __restrict__ W,
                        const float* __restrict__ bvec,
                        float* __restrict__ out)
{
    extern __shared__ uint32_t sm[];
    float4* wb4 = (float4*)(sm + WB4_OFF);
    uint4*  BQ4 = (uint4*)(sm + B_OFF);

    const int tid  = threadIdx.x;
    const int wid  = tid >> 5;
    const int lane = tid & 31;
    const int bidx = blockIdx.x >> 4;          // 16 tiles per batch
    const int l0   = (blockIdx.x & 15) << 9;   // 512 rows per tile
    const float* xb = x + (size_t)bidx * (LLEN * CIN);

    // ---- stage B (CTA-shared): unit (lg, kb, i) ----
    for (int u = tid; u < 32 * 24 * 4; u += 512) {
        int i  = u & 3;
        int t2 = u >> 2;
        int kb = t2 % 24;
        int lg = t2 / 24;                      // 0..31
        int q4g = lg >> 2, s4g = lg & 3;
        int n0 = 16 * i + q4g;
        int n1 = n0 + 8;
        int p0 = kb * 8 + s4g, p2 = p0 + 4;
        uint4 w;
        w.x = h2pack(slotW(W, n0, p0, 0), slotW(W, n0, p0, 1));
        w.y = h2pack(slotW(W, n0, p2, 0), slotW(W, n0, p2, 1));
        w.z = h2pack(slotW(W, n1, p0, 0), slotW(W, n1, p0, 1));
        w.w = h2pack(slotW(W, n1, p2, 0), slotW(W, n1, p2, 1));
        BQ4[lg * LGSTR + kb * 4 + i] = w;
    }
    // ---- fp32 time-weight + bias pairs ----
    if (tid < 32) {
        wb4[tid] = make_float4(W[(size_t)(2 * tid) * 316], bvec[2 * tid],
                               W[(size_t)(2 * tid + 1) * 316], bvec[2 * tid + 1]);
    }
    __syncthreads();   // the ONLY CTA-wide barrier

    // ---- warp-private xp staging: 36 rows (32 + 4 halo), row-pair packed ----
    const int wrow   = wid * 32;
    const int wpbase = wid * WPRIV;
    {
        const int gbase = l0 + wrow - 2;
#pragma unroll
        for (int j = 0; j < 18; j++) {
            int u  = j * 32 + lane;
            int r  = u >> 4, c4 = u & 15;
            int g  = gbase + r;
            float4 v0, v1;
            if ((unsigned)g < (unsigned)LLEN) v0 = *(const float4*)(xb + (size_t)g * CIN + c4 * 4);
            else { v0 = make_float4(0.f, 0.f, 0.f, 0.f); if (c4 == 0) v0.x = 1.0f; }
            if ((unsigned)(g + 1) < (unsigned)LLEN) v1 = *(const float4*)(xb + (size_t)(g + 1) * CIN + c4 * 4);
            else { v1 = make_float4(0.f, 0.f, 0.f, 0.f); if (c4 == 0) v1.x = 1.0f; }
            uint4 pw;
            pw.x = h2pack(v0.x, v1.x); pw.y = h2pack(v0.y, v1.y);
            pw.z = h2pack(v0.z, v1.z); pw.w = h2pack(v0.w, v1.w);
            *(uint4*)(sm + wpbase + r * XPS + c4 * 4) = pw;
        }
        // zero pad columns 64..67 (read when channel slot = 64, B is zero there)
        for (int r = lane; r < 36; r += 32)
            *(uint4*)(sm + wpbase + r * XPS + 64) = make_uint4(0, 0, 0, 0);
    }
    __syncwarp();

    // ---- mainloop: warp tile 32 rows x 64 cols, 24 k-blocks ----
    const int q4 = lane >> 2;
    const int s4 = lane & 3;
    const int bx = wpbase + q4 * XPS + s4;     // A base (word index)
    const int ub = (q4 * 4 + s4) * LGSTR;      // B base (uint4 index)

    float d[2][8][4];
#pragma unroll
    for (int m = 0; m < 2; m++)
#pragma unroll
        for (int nb = 0; nb < 8; nb++)
            d[m][nb][0] = d[m][nb][1] = d[m][nb][2] = d[m][nb][3] = 0.f;

#pragma unroll
    for (int kb = 0; kb < 24; kb++) {
        const int sub0 = 2 * kb, sub1 = 2 * kb + 1;
        const int kk0 = 2 * (sub0 % 3), cb0 = 4 * (sub0 / 3) + 1;
        const int kk1 = 2 * (sub1 % 3), cb1 = 4 * (sub1 / 3) + 1;

        uint4 b0 = BQ4[ub + kb * 4 + 0];
        uint4 b1 = BQ4[ub + kb * 4 + 1];
        uint4 b2 = BQ4[ub + kb * 4 + 2];
        uint4 b3 = BQ4[ub + kb * 4 + 3];

#pragma unroll
        for (int m = 0; m < 2; m++) {
            uint32_t a[4];
            a[0] = sm[bx + (kk0 + 16 * m) * XPS + cb0];
            a[1] = sm[bx + (kk0 + 16 * m + 8) * XPS + cb0];
            a[2] = sm[bx + (kk1 + 16 * m) * XPS + cb1];
            a[3] = sm[bx + (kk1 + 16 * m + 8) * XPS + cb1];
            mma_f16(d[m][0], a, b0.x, b0.y);
            mma_f16(d[m][1], a, b0.z, b0.w);
            mma_f16(d[m][2], a, b1.x, b1.y);
            mma_f16(d[m][3], a, b1.z, b1.w);
            mma_f16(d[m][4], a, b2.x, b2.y);
            mma_f16(d[m][5], a, b2.z, b2.w);
            mma_f16(d[m][6], a, b3.x, b3.y);
            mma_f16(d[m][7], a, b3.z, b3.w);
        }
    }

    // ---- epilogue: + W[:,0]*t_resc + b, Lorentz norm (in-warp over s4), store ----
#pragma unroll
    for (int m = 0; m < 2; m++) {
        const int ra = wrow + 16 * m + q4;
        const float tra = tresc(xb, l0 + ra);
        const float trb = tresc(xb, l0 + ra + 8);
        float ssa = 0.f, ssb = 0.f;
#pragma unroll
        for (int nb = 0; nb < 8; nb++) {
            float4 f4 = wb4[nb * 4 + s4];
            float y0 = fmaf(f4.x, tra, d[m][nb][0]) + f4.y;
            float y1 = fmaf(f4.z, tra, d[m][nb][1]) + f4.w;
            float y2 = fmaf(f4.x, trb, d[m][nb][2]) + f4.y;
            float y3 = fmaf(f4.z, trb, d[m][nb][3]) + f4.w;
            if (!(nb == 0 && s4 == 0)) {       // global col 0 excluded from the norm
                ssa = fmaf(y0, y0, ssa);
                ssb = fmaf(y2, y2, ssb);
            }
            ssa = fmaf(y1, y1, ssa);
            ssb = fmaf(y3, y3, ssb);
            d[m][nb][0] = y0; d[m][nb][1] = y1;
            d[m][nb][2] = y2; d[m][nb][3] = y3;
        }
        ssa += __shfl_xor_sync(0xffffffffu, ssa, 1);
        ssa += __shfl_xor_sync(0xffffffffu, ssa, 2);
        ssb += __shfl_xor_sync(0xffffffffu, ssb, 1);
        ssb += __shfl_xor_sync(0xffffffffu, ssb, 2);
        if (s4 == 0) {
            d[m][0][0] = sqrtf(ssa + 1.0f);
            d[m][0][2] = sqrtf(ssb + 1.0f);
        }

        const size_t oa = ((size_t)bidx * LLEN + (size_t)(l0 + ra)) * 64 + 2 * s4;
        const size_t ob = oa + 8 * 64;
#pragma unroll
        for (int nb = 0; nb < 8; nb++) {
            *(float2*)(out + oa + nb * 8) = make_float2(d[m][nb][0], d[m][nb][1]);
            *(float2*)(out + ob + nb * 8) = make_float2(d[m][nb][2], d[m][nb][3]);
        }
    }
}

extern "C" void kernel_launch(void* const* d_in, const int* in_sizes, int n_in,
                              void* d_out, int out_size)
{
    const float* x = (const float*)d_in[0];
    const float* W = (const float*)d_in[1];
    const float* b = (const float*)d_in[2];
    float* out = (float*)d_out;

    cudaFuncSetAttribute(lorentz_f16_kernel,
                         cudaFuncAttributeMaxDynamicSharedMemorySize, SMEM_BYTES);
    lorentz_f16_kernel<<<256, 512, SMEM_BYTES>>>(x, W, b, out);
}